// round 1
// baseline (speedup 1.0000x reference)
#include <cuda_runtime.h>
#include <math.h>

// ---------------- problem constants ----------------
#define BB 64
#define TT 100

#define N1 (64*16*32*48)
#define N2 (64*32*16*24)
#define N3 (64*64*8*12)

// ---------------- device scratch (no allocs allowed) ----------------
__device__ __align__(16) float g_w1p[425*64];
__device__ __align__(16) float g_w2p[432*128];
__device__ __align__(16) float g_w3p[864*256];
__device__ __align__(16) float g_b1p[64];
__device__ __align__(16) float g_b2p[128];
__device__ __align__(16) float g_b3p[256];
__device__ __align__(16) float g_fw1T[1536*128];

__device__ __align__(16) float g_mem1[2*N1];
__device__ __align__(16) float g_syn1[N1];
__device__ __align__(16) float g_mem2[2*N2];
__device__ __align__(16) float g_syn2[N2];
__device__ __align__(16) float g_mem3[2*N3];
__device__ __align__(16) float g_syn3[N3];
__device__ __align__(16) float g_mem4[64*128];
__device__ __align__(16) float g_mem5[64*2];

__device__ __forceinline__ float sigmoidf_(float v) {
    return 1.0f / (1.0f + expf(-v));
}

// ---------------- prep kernels (run inside the graph, deterministic) ----------------
__global__ void k_zero(float* p, int n) {
    for (int i = blockIdx.x*blockDim.x + threadIdx.x; i < n; i += gridDim.x*blockDim.x)
        p[i] = 0.0f;
}

// w: [4*CELLS][Kdim] OIHW-flattened, gate-major (i|f|g|o blocks).
// wp: [Kdim][4*CELLS] with oc' = cell*4 + gate (K-major GEMM A, cell-interleaved).
__global__ void k_permute_w(const float* __restrict__ w, float* __restrict__ wp,
                            int CELLS, int Kdim) {
    int MTOT = CELLS*4;
    int total = MTOT*Kdim;
    for (int idx = blockIdx.x*blockDim.x + threadIdx.x; idx < total; idx += gridDim.x*blockDim.x) {
        int k = idx / MTOT;
        int ocp = idx - k*MTOT;
        int cell = ocp >> 2, gate = ocp & 3;
        wp[idx] = w[(size_t)(gate*CELLS + cell)*Kdim + k];
    }
}

__global__ void k_permute_b(const float* __restrict__ b, float* __restrict__ bp, int CELLS) {
    int MTOT = CELLS*4;
    for (int ocp = blockIdx.x*blockDim.x + threadIdx.x; ocp < MTOT; ocp += gridDim.x*blockDim.x) {
        int cell = ocp >> 2, gate = ocp & 3;
        bp[ocp] = b[gate*CELLS + cell];
    }
}

__global__ void k_transpose_fc(const float* __restrict__ fw1, float* __restrict__ fw1T) {
    int total = 128*1536;
    for (int idx = blockIdx.x*blockDim.x + threadIdx.x; idx < total; idx += gridDim.x*blockDim.x) {
        int n = idx >> 7, j = idx & 127;
        fw1T[idx] = fw1[(size_t)j*1536 + n];
    }
}

// ---------------- fused conv-LSTM step kernel ----------------
// One block: 64 permuted output channels (16 complete cells) x (TH x TW) spatial tile,
// for one batch image. GEMM over Kdim = CIN*KW*KW with input tile + weight chunks in smem.
// Epilogue fuses gate activations + synaptic/membrane state update.
// IN_MODE: 0 = raw float input (x_t), 1 = maxpool2+spike from upper mem, 2 = avgpool2+spike.
template<int CX, int CM, int KW, int HH, int WW, int TH, int TW, int MTOT, int IN_MODE, int KCH_IC>
__global__ void __launch_bounds__(16*TH)
conv_step(const float* __restrict__ src, int src_bstride,
          const float* __restrict__ memp,
          float* __restrict__ syn, float* __restrict__ memn,
          const float* __restrict__ wk, const float* __restrict__ bp)
{
    constexpr int CIN = CX + CM;
    constexpr int KK = KW*KW;
    constexpr int Kdim = CIN*KK;
    constexpr int PAD = KW/2;
    constexpr int IH = TH + KW - 1;
    constexpr int IW = TW + KW - 1;
    constexpr int RN = TW;          // thread covers a full tile row
    constexpr int RM = 4;           // 4 gates of one cell
    constexpr int TM = 16;
    constexpr int THREADS = TM*TH;
    constexpr int NTX = WW / TW;
    constexpr int KCH = KCH_IC * KK;

    extern __shared__ float smem[];
    float* sin = smem;                    // CIN*IH*IW
    float* sw  = smem + CIN*IH*IW;        // KCH*64

    const int tid = threadIdx.x;
    const int tileY = blockIdx.x / NTX;
    const int tileX = blockIdx.x - tileY*NTX;
    const int oy0 = tileY*TH, ox0 = tileX*TW;
    const int mtile = blockIdx.y;
    const int b = blockIdx.z;

    // ---- load input tile (with SAME zero-pad halo); fuse pooling+spike for modes 1/2 ----
    for (int idx = tid; idx < CIN*IH*IW; idx += THREADS) {
        int c = idx / (IH*IW);
        int r = idx - c*(IH*IW);
        int iy = r / IW, ix = r - iy*IW;
        int gy = oy0 + iy - PAD, gx = ox0 + ix - PAD;
        float v = 0.0f;
        if (gy >= 0 && gy < HH && gx >= 0 && gx < WW) {
            if (c < CX) {
                if (IN_MODE == 0) {
                    v = src[(size_t)b*src_bstride + gy*WW + gx];
                } else {
                    const float* p = src + (((size_t)b*CX + c)*(2*HH) + 2*gy)*(size_t)(2*WW) + 2*gx;
                    float a0 = p[0], a1 = p[1], a2 = p[2*WW], a3 = p[2*WW+1];
                    float pl = (IN_MODE == 1) ? fmaxf(fmaxf(a0,a1), fmaxf(a2,a3))
                                              : 0.25f*(a0+a1+a2+a3);
                    v = (pl > 1.0f) ? 1.0f : 0.0f;
                }
            } else {
                v = memp[(((size_t)b*CM + (c - CX))*HH + gy)*(size_t)WW + gx];
            }
        }
        sin[idx] = v;
    }

    const int tm = tid & (TM-1);
    const int tn = tid / TM;       // tile row
    const int m0 = tm * RM;

    float acc[RM][RN];
    #pragma unroll
    for (int i = 0; i < RM; i++)
        #pragma unroll
        for (int j = 0; j < RN; j++) acc[i][j] = 0.0f;

    // ---- GEMM main loop over k chunks ----
    for (int kc = 0; kc < Kdim; kc += KCH) {
        const int kend = (Kdim - kc < KCH) ? (Kdim - kc) : KCH;
        __syncthreads();
        for (int i = tid; i < kend*64; i += THREADS) {
            int kr = i >> 6, mm = i & 63;
            sw[i] = wk[(size_t)(kc + kr)*MTOT + mtile*64 + mm];
        }
        __syncthreads();
        const int nic = kend / KK;
        const int ic0 = kc / KK;
        for (int ici = 0; ici < nic; ici++) {
            const float* sbase = sin + (ic0 + ici)*(IH*IW);
            const float* wbase = sw + ici*(KK*64) + m0;
            #pragma unroll
            for (int ky = 0; ky < KW; ky++) {
                #pragma unroll
                for (int kx = 0; kx < KW; kx++) {
                    const float4 w4 = *(const float4*)(wbase + (ky*KW + kx)*64);
                    const float* arow = sbase + (tn + ky)*IW + kx;
                    #pragma unroll
                    for (int j = 0; j < RN; j++) {
                        float a = arow[j];
                        acc[0][j] = fmaf(w4.x, a, acc[0][j]);
                        acc[1][j] = fmaf(w4.y, a, acc[1][j]);
                        acc[2][j] = fmaf(w4.z, a, acc[2][j]);
                        acc[3][j] = fmaf(w4.w, a, acc[3][j]);
                    }
                }
            }
        }
    }

    // ---- epilogue: gates -> syn/mem state update (this thread owns one full cell) ----
    const int cell = mtile*16 + tm;
    const float4 bb = *(const float4*)(bp + mtile*64 + m0);
    size_t base = (((size_t)b*CM + cell)*HH + (oy0 + tn))*(size_t)WW + ox0;
    #pragma unroll
    for (int j = 0; j < RN; j++) {
        float zi = acc[0][j] + bb.x;
        float zf = acc[1][j] + bb.y;
        float zg = acc[2][j] + bb.z;
        float zo = acc[3][j] + bb.w;
        float sv = syn[base + j];
        float sn = sigmoidf_(zf)*sv + sigmoidf_(zi)*tanhf(zg);
        syn[base + j]  = sn;
        memn[base + j] = sigmoidf_(zo)*tanhf(sn);
    }
}

// ---------------- fused FC head: avgpool+spike -> fc1 -> leaky -> fc2 -> leaky -> out ----------------
__global__ void __launch_bounds__(128)
fc_step(const float* __restrict__ mem3n,
        const float* __restrict__ fw1T, const float* __restrict__ fb1,
        const float* __restrict__ fw2,  const float* __restrict__ fb2,
        float* __restrict__ mem4, float* __restrict__ mem5,
        float* __restrict__ out, int t)
{
    __shared__ float spk[1536];
    __shared__ float red[8];
    const int b = blockIdx.x;
    const int tid = threadIdx.x;

    // spk3 = (avgpool2(mem3) > 1), flattened C(64) x H(4) x W(6)
    for (int n = tid; n < 1536; n += 128) {
        int c = n / 24, r = n - c*24;
        int h = r / 6, w = r - h*6;
        const float* p = mem3n + (((size_t)b*64 + c)*8 + 2*h)*12 + 2*w;
        float s = 0.25f*(p[0] + p[1] + p[12] + p[13]);
        spk[n] = (s > 1.0f) ? 1.0f : 0.0f;
    }
    __syncthreads();

    // fc1 (binary input -> masked column sum, warp-uniform branch skips dead rows)
    float acc = 0.0f;
    for (int n = 0; n < 1536; n++) {
        if (spk[n] != 0.0f) acc += fw1T[(size_t)n*128 + tid];
    }
    float cur = acc + fb1[tid];

    // leaky 1 (reset from prior mem, subtract)
    float m = mem4[b*128 + tid];
    float reset = (m > 1.0f) ? 1.0f : 0.0f;
    m = 0.9f*m + cur - reset;
    mem4[b*128 + tid] = m;
    float sp4 = (m > 1.0f) ? 1.0f : 0.0f;

    // fc2 (2 outputs) via block reduction
    float v0 = sp4 * fw2[tid];
    float v1 = sp4 * fw2[128 + tid];
    #pragma unroll
    for (int off = 16; off > 0; off >>= 1) {
        v0 += __shfl_down_sync(0xffffffffu, v0, off);
        v1 += __shfl_down_sync(0xffffffffu, v1, off);
    }
    if ((tid & 31) == 0) { red[tid >> 5] = v0; red[4 + (tid >> 5)] = v1; }
    __syncthreads();

    if (tid < 2) {
        const float* rr = red + tid*4;
        float cur2 = rr[0] + rr[1] + rr[2] + rr[3] + fb2[tid];
        float m5 = mem5[b*2 + tid];
        float rs = (m5 > 1.0f) ? 1.0f : 0.0f;
        m5 = 0.9f*m5 + cur2 - rs;
        mem5[b*2 + tid] = m5;
        float s5 = (m5 > 1.0f) ? 1.0f : 0.0f;
        out[(size_t)t*128 + b*2 + tid] = s5;                 // spk_rec [T,B,2]
        out[12800 + (size_t)t*128 + b*2 + tid] = m5;         // mem_rec [T,B,2]
    }
}

// ---------------- host ----------------
extern "C" void kernel_launch(void* const* d_in, const int* in_sizes, int n_in,
                              void* d_out, int out_size)
{
    const float* x   = (const float*)d_in[0];
    const float* w1  = (const float*)d_in[1];
    const float* b1  = (const float*)d_in[2];
    const float* w2  = (const float*)d_in[3];
    const float* b2  = (const float*)d_in[4];
    const float* w3  = (const float*)d_in[5];
    const float* b3  = (const float*)d_in[6];
    const float* fw1 = (const float*)d_in[7];
    const float* fb1 = (const float*)d_in[8];
    const float* fw2 = (const float*)d_in[9];
    const float* fb2 = (const float*)d_in[10];
    float* out = (float*)d_out;

    float *w1p, *w2p, *w3p, *b1p, *b2p, *b3p, *fw1T;
    float *mem1, *syn1, *mem2, *syn2, *mem3, *syn3, *mem4, *mem5;
    cudaGetSymbolAddress((void**)&w1p,  g_w1p);
    cudaGetSymbolAddress((void**)&w2p,  g_w2p);
    cudaGetSymbolAddress((void**)&w3p,  g_w3p);
    cudaGetSymbolAddress((void**)&b1p,  g_b1p);
    cudaGetSymbolAddress((void**)&b2p,  g_b2p);
    cudaGetSymbolAddress((void**)&b3p,  g_b3p);
    cudaGetSymbolAddress((void**)&fw1T, g_fw1T);
    cudaGetSymbolAddress((void**)&mem1, g_mem1);
    cudaGetSymbolAddress((void**)&syn1, g_syn1);
    cudaGetSymbolAddress((void**)&mem2, g_mem2);
    cudaGetSymbolAddress((void**)&syn2, g_syn2);
    cudaGetSymbolAddress((void**)&mem3, g_mem3);
    cudaGetSymbolAddress((void**)&syn3, g_syn3);
    cudaGetSymbolAddress((void**)&mem4, g_mem4);
    cudaGetSymbolAddress((void**)&mem5, g_mem5);

    // smem sizes
    const int S1 = (17*12*12 + 150*64) * 4;   // 48192 B
    const int S2 = (48*10*10 + 144*64) * 4;   // 56064 B
    const int S3 = (96*10*14 + 144*64) * 4;   // 90624 B

    auto c1 = conv_step<1, 16, 5, 32, 48, 8, 8,  64,  0, 6>;
    auto c2 = conv_step<16,32, 3, 16, 24, 8, 8,  128, 1, 16>;
    auto c3 = conv_step<32,64, 3, 8,  12, 8, 12, 256, 2, 16>;
    cudaFuncSetAttribute(c1, cudaFuncAttributeMaxDynamicSharedMemorySize, S1);
    cudaFuncSetAttribute(c2, cudaFuncAttributeMaxDynamicSharedMemorySize, S2);
    cudaFuncSetAttribute(c3, cudaFuncAttributeMaxDynamicSharedMemorySize, S3);

    // ---- prep: zero states + permute weights (inside graph, deterministic) ----
    k_zero<<<256, 256>>>(mem1, N1);   // ping buffer 0
    k_zero<<<256, 256>>>(syn1, N1);
    k_zero<<<256, 256>>>(mem2, N2);
    k_zero<<<256, 256>>>(syn2, N2);
    k_zero<<<128, 256>>>(mem3, N3);
    k_zero<<<128, 256>>>(syn3, N3);
    k_zero<<<32,  256>>>(mem4, 64*128);
    k_zero<<<1,   128>>>(mem5, 64*2);

    k_permute_w<<<128, 256>>>(w1, w1p, 16, 425);
    k_permute_w<<<256, 256>>>(w2, w2p, 32, 432);
    k_permute_w<<<512, 256>>>(w3, w3p, 64, 864);
    k_permute_b<<<1, 64>>>(b1, b1p, 16);
    k_permute_b<<<1, 128>>>(b2, b2p, 32);
    k_permute_b<<<1, 256>>>(b3, b3p, 64);
    k_transpose_fc<<<512, 256>>>(fw1, fw1T);

    // ---- time loop: 4 fused kernels per step ----
    for (int t = 0; t < TT; t++) {
        const int pr = t & 1;
        const int nx = 1 - pr;
        c1<<<dim3(24, 1, 64), 128, S1>>>(x + (size_t)t*(32*48), TT*32*48,
                                         mem1 + (size_t)pr*N1, syn1, mem1 + (size_t)nx*N1,
                                         w1p, b1p);
        c2<<<dim3(6, 2, 64), 128, S2>>>(mem1 + (size_t)nx*N1, 0,
                                        mem2 + (size_t)pr*N2, syn2, mem2 + (size_t)nx*N2,
                                        w2p, b2p);
        c3<<<dim3(1, 4, 64), 128, S3>>>(mem2 + (size_t)nx*N2, 0,
                                        mem3 + (size_t)pr*N3, syn3, mem3 + (size_t)nx*N3,
                                        w3p, b3p);
        fc_step<<<64, 128>>>(mem3 + (size_t)nx*N3, fw1T, fb1, fw2, fb2,
                             mem4, mem5, out, t);
    }
}

// round 2
// speedup vs baseline: 4242.9169x; 4242.9169x over previous
#include <cuda_runtime.h>

// ConvLSTMSNN — exact dead-code-eliminated form.
//
// Proof sketch (fp32 semantics of the reference):
//   mem_k = sigmoid(o) * tanh(syn)  =>  mem_k <= 1.0f exactly (both factors
//   saturate at 1.0f, product of values <=1 rounds to <=1).
//   maxpool2(mem) <= 1.0f; avgpool2(mem) = 0.25f*sum4 <= 1.0f (sum4 rounding
//   error < 3.6e-7 cannot exceed 4.0f's next representable, and 4.0f*0.25f==1.0f).
//   spike = heaviside(pool - 1.0f) with strict '>'  =>  spk1=spk2=spk3 == 0
//   for every timestep, every input, every weight.
// Hence cur = 0 @ fw1^T + fb1 = fb1 exactly, and the output (spk_rec, mem_rec)
// is fully determined by the two Leaky layers driven by the constant fb1,
// identical across the batch dimension. We simulate exactly that.
//
// Round-1 kernel (full conv stack computed) matched the reference with
// rel_err == 0.0 bitwise — corroborating this structure empirically.

#define TT 100

__global__ void __launch_bounds__(32)
snn_head_kernel(const float* __restrict__ fb1,
                const float* __restrict__ fw2,
                const float* __restrict__ fb2,
                float* __restrict__ out)
{
    const int lane = threadIdx.x;              // 0..31, owns dims lane*4..lane*4+3

    const float4 b4  = ((const float4*)fb1)[lane];
    const float4 w04 = ((const float4*)fw2)[lane];          // fw2[0][:]
    const float4 w14 = ((const float4*)(fw2 + 128))[lane];  // fw2[1][:]
    const float fb2_0 = fb2[0];
    const float fb2_1 = fb2[1];

    float b[4]  = {b4.x,  b4.y,  b4.z,  b4.w};
    float w0[4] = {w04.x, w04.y, w04.z, w04.w};
    float w1[4] = {w14.x, w14.y, w14.z, w14.w};

    float m4[4] = {0.f, 0.f, 0.f, 0.f};   // mem4 (Leaky layer 1), per-dim
    float m5_0 = 0.f, m5_1 = 0.f;         // mem5 (Leaky layer 2), replicated per lane

    for (int t = 0; t < TT; t++) {
        // ---- Leaky 1: mem4 = 0.9*mem4 + fb1 - (mem4_prev > 1); spk4 = (mem4 > 1) ----
        float v0 = 0.f, v1 = 0.f;
        #pragma unroll
        for (int i = 0; i < 4; i++) {
            float reset = (m4[i] > 1.0f) ? 1.0f : 0.0f;
            m4[i] = 0.9f * m4[i] + b[i] - reset;
            float s4 = (m4[i] > 1.0f) ? 1.0f : 0.0f;   // (m-1 > 0) <=> (m > 1)
            v0 += s4 * w0[i];
            v1 += s4 * w1[i];
        }

        // ---- fc2: butterfly reduce so every lane holds both dot products ----
        #pragma unroll
        for (int off = 16; off; off >>= 1) {
            v0 += __shfl_xor_sync(0xffffffffu, v0, off);
            v1 += __shfl_xor_sync(0xffffffffu, v1, off);
        }
        const float cur0 = v0 + fb2_0;
        const float cur1 = v1 + fb2_1;

        // ---- Leaky 2 (redundant in every lane) ----
        float r0 = (m5_0 > 1.0f) ? 1.0f : 0.0f;
        float r1 = (m5_1 > 1.0f) ? 1.0f : 0.0f;
        m5_0 = 0.9f * m5_0 + cur0 - r0;
        m5_1 = 0.9f * m5_1 + cur1 - r1;
        const float s0 = (m5_0 > 1.0f) ? 1.0f : 0.0f;
        const float s1 = (m5_1 > 1.0f) ? 1.0f : 0.0f;

        // ---- broadcast across batch: out layout [spk_rec | mem_rec], each [T,B,2] ----
        const float4 sv = make_float4(s0, s1, s0, s1);
        const float4 mv = make_float4(m5_0, m5_1, m5_0, m5_1);
        ((float4*)(out + (size_t)t * 128))[lane] = sv;
        ((float4*)(out + 12800 + (size_t)t * 128))[lane] = mv;
    }
}

extern "C" void kernel_launch(void* const* d_in, const int* in_sizes, int n_in,
                              void* d_out, int out_size)
{
    // inputs (metadata order): x, w1, b1, w2, b2, w3, b3, fw1, fb1, fw2, fb2
    const float* fb1 = (const float*)d_in[8];
    const float* fw2 = (const float*)d_in[9];
    const float* fb2 = (const float*)d_in[10];
    float* out = (float*)d_out;

    snn_head_kernel<<<1, 32>>>(fb1, fw2, fb2, out);
}